// round 14
// baseline (speedup 1.0000x reference)
#include <cuda_runtime.h>
#include <cuda_fp16.h>
#include <math.h>
#include <stdint.h>

#define EE 512
#define HH 8
#define BB 4
#define SS 2048
#define NROW (BB*SS)            // 8192
#define FF 2048                 // 2LH + 2AH
#define LH 512

// qkv packed layout per row: V @0, Q @512, K @1024 (halves)
#define QKV_W 1536
#define QO_V 0
#define QO_Q 512
#define QO_K 1024

// Scratch (allocation-free rule: __device__ globals)
__device__ __half g_normed[(size_t)NROW*EE];   // 8.4 MB
__device__ __half g_Wt[(size_t)FF*EE];         // 2 MB (W transposed, fp16)
__device__ __half g_qkv[(size_t)NROW*QKV_W];   // 25 MB (V,Q,K fp16)
__device__ float  g_u[(size_t)NROW*LH];        // 16.8 MB (U fp32)
__device__ float  g_attn[(size_t)NROW*LH];     // 16.8 MB

// ---------------- helpers ----------------
__device__ __forceinline__ uint32_t h2u(__half2 h) {
    uint32_t u;
    memcpy(&u, &h, 4);
    return u;
}
__device__ __forceinline__ __half2 u2h(uint32_t u) {
    __half2 h;
    memcpy(&h, &u, 4);
    return h;
}
// silu on packed half2: y = 0.5x + 0.5x*tanh(0.5x)  (exact tails via tanh saturation)
__device__ __forceinline__ uint32_t silu2(uint32_t x2) {
    __half2 x = u2h(x2);
    __half2 hx = __hmul2(x, __half2half2(__float2half(0.5f)));
    uint32_t hxu = h2u(hx), thu;
    asm("tanh.approx.f16x2 %0, %1;" : "=r"(thu) : "r"(hxu));
    __half2 y = __hfma2(hx, u2h(thu), hx);
    return h2u(y);
}
__device__ __forceinline__ void cpa16(void* dst, const void* src) {
    unsigned u = (unsigned)__cvta_generic_to_shared(dst);
    asm volatile("cp.async.cg.shared.global [%0], [%1], 16;\n" :: "r"(u), "l"(src));
}
__device__ __forceinline__ void cp_commit() { asm volatile("cp.async.commit_group;\n"); }
__device__ __forceinline__ void cp_wait0() { asm volatile("cp.async.wait_group 0;\n"); }
__device__ __forceinline__ void cp_wait1() { asm volatile("cp.async.wait_group 1;\n"); }

__device__ __forceinline__ uint32_t smem_u32(const void* p) {
    return (uint32_t)__cvta_generic_to_shared(p);
}
__device__ __forceinline__ void ldsm_x4(uint32_t* r, uint32_t addr) {
    asm volatile("ldmatrix.sync.aligned.m8n8.x4.shared.b16 {%0,%1,%2,%3}, [%4];"
                 : "=r"(r[0]), "=r"(r[1]), "=r"(r[2]), "=r"(r[3]) : "r"(addr));
}
__device__ __forceinline__ void ldsm_x4_t(uint32_t* r, uint32_t addr) {
    asm volatile("ldmatrix.sync.aligned.m8n8.x4.trans.shared.b16 {%0,%1,%2,%3}, [%4];"
                 : "=r"(r[0]), "=r"(r[1]), "=r"(r[2]), "=r"(r[3]) : "r"(addr));
}
__device__ __forceinline__ void mma_f16(float* d, const uint32_t* a, const uint32_t* b) {
    asm volatile(
        "mma.sync.aligned.m16n8k16.row.col.f32.f16.f16.f32 "
        "{%0,%1,%2,%3}, {%4,%5,%6,%7}, {%8,%9}, {%0,%1,%2,%3};\n"
        : "+f"(d[0]), "+f"(d[1]), "+f"(d[2]), "+f"(d[3])
        : "r"(a[0]), "r"(a[1]), "r"(a[2]), "r"(a[3]), "r"(b[0]), "r"(b[1]));
}
// f16 accumulation; D-fragment layout == A-fragment layout of next mma
__device__ __forceinline__ void mma_f16acc(uint32_t* d, const uint32_t* a, const uint32_t* b) {
    asm volatile(
        "mma.sync.aligned.m16n8k16.row.col.f16.f16.f16.f16 "
        "{%0,%1}, {%2,%3,%4,%5}, {%6,%7}, {%0,%1};\n"
        : "+r"(d[0]), "+r"(d[1])
        : "r"(a[0]), "r"(a[1]), "r"(a[2]), "r"(a[3]), "r"(b[0]), "r"(b[1]));
}

__device__ __forceinline__ float2 block_reduce_sum2_128(float sum, float sq) {
    __shared__ float sh[8];
    int lane = threadIdx.x & 31, w = threadIdx.x >> 5;
#pragma unroll
    for (int o = 16; o > 0; o >>= 1) {
        sum += __shfl_xor_sync(0xffffffffu, sum, o);
        sq  += __shfl_xor_sync(0xffffffffu, sq, o);
    }
    if (lane == 0) { sh[w] = sum; sh[4 + w] = sq; }
    __syncthreads();
    float s = 0.f, q = 0.f;
#pragma unroll
    for (int i = 0; i < 4; i++) { s += sh[i]; q += sh[4 + i]; }
    return make_float2(s, q);
}

// ---------------- 1) input LayerNorm (fp16 out, float4 loads) ----------------
__global__ __launch_bounds__(128) void ln_in_kernel(const float* __restrict__ x,
                                                    const float* __restrict__ g,
                                                    const float* __restrict__ be) {
    const int row = blockIdx.x, t = threadIdx.x;
    const float4 v = *(const float4*)&x[(size_t)row * EE + 4 * t];
    float2 r = block_reduce_sum2_128(v.x + v.y + v.z + v.w,
                                     v.x * v.x + v.y * v.y + v.z * v.z + v.w * v.w);
    float mu = r.x * (1.f / 512.f);
    float var = r.y * (1.f / 512.f) - mu * mu;
    float rs = rsqrtf(var + 1e-6f);
    const float4 gg = *(const float4*)&g[4 * t];
    const float4 bb = *(const float4*)&be[4 * t];
    __half2 y0 = __floats2half2_rn((v.x - mu) * rs * gg.x + bb.x, (v.y - mu) * rs * gg.y + bb.y);
    __half2 y1 = __floats2half2_rn((v.z - mu) * rs * gg.z + bb.z, (v.w - mu) * rs * gg.w + bb.w);
    __half2* orow = (__half2*)(g_normed + (size_t)row * EE);
    orow[2 * t] = y0; orow[2 * t + 1] = y1;
}

// ---------------- 1b) transpose W [E,FF] -> g_Wt [FF,E] fp16 ----------------
__global__ __launch_bounds__(256) void transpose_w_kernel(const float* __restrict__ W) {
    __shared__ float tile[32][33];
    const int tx = threadIdx.x, ty = threadIdx.y;   // 32 x 8
    const int n0 = blockIdx.x * 32, k0 = blockIdx.y * 32;
#pragma unroll
    for (int j = 0; j < 4; j++)
        tile[ty + j * 8][tx] = W[(size_t)(k0 + ty + j * 8) * FF + n0 + tx];
    __syncthreads();
#pragma unroll
    for (int j = 0; j < 4; j++)
        g_Wt[(size_t)(n0 + ty + j * 8) * EE + k0 + tx] = __float2half(tile[tx][ty + j * 8]);
}

// ---------------- 2) projection GEMM (fp16 mma m16n8k16 + ldmatrix) ----------------
// 128x128 tile, BK=64, 256 threads = 8 warps (2m x 4n), warp tile 64x32.
// __launch_bounds__(256, 2): cap 128 regs -> 2 blocks/SM -> 4 warps/SMSP latency hiding.
// Epilogue: QKV tiles staged via smem for 16B-coalesced global stores.
#define PROJ_SMEM (4 * 128 * 72 * 2)   // 73728 B
__global__ __launch_bounds__(256, 2) void gemm_proj_kernel() {
    extern __shared__ __half sh[];
    const int t = threadIdx.x;
    const int wid = t >> 5, lane = t & 31;
    const int gid = lane >> 2, tig = lane & 3;
    const int warp_m = wid & 1, warp_n = wid >> 1;
    const int m0 = warp_m * 64, n0 = warp_n * 32;
    const int bm = blockIdx.y * 128, bn = blockIdx.x * 128;

    float acc[4][4][4] = {};

#define PJ_LOAD(st, k0) do {                                                           \
        __half* sA = sh + (st) * 9216;                                                 \
        __half* sB = sh + 18432 + (st) * 9216;                                         \
        _Pragma("unroll")                                                              \
        for (int i = 0; i < 4; i++) {                                                  \
            const int gidx = t + i * 256;                                              \
            const int row = gidx >> 3, q = gidx & 7;                                   \
            cpa16(sA + row * 72 + q * 8, &g_normed[(size_t)(bm + row) * EE + (k0) + q * 8]); \
            cpa16(sB + row * 72 + q * 8, &g_Wt[(size_t)(bn + row) * EE + (k0) + q * 8]);    \
        }                                                                              \
    } while (0)

    PJ_LOAD(0, 0); cp_commit();

    for (int it = 0; it < 8; ++it) {
        if (it < 7) { PJ_LOAD((it + 1) & 1, (it + 1) * 64); cp_commit(); cp_wait1(); }
        else cp_wait0();
        __syncthreads();
        const int st = it & 1;
        const uint32_t aBase = smem_u32(sh + st * 9216);
        const uint32_t bBase = smem_u32(sh + 18432 + st * 9216);
#pragma unroll
        for (int ks = 0; ks < 4; ks++) {
            const int k0h = ks * 16;
            uint32_t af[4][4], bf[2][4];
#pragma unroll
            for (int mi = 0; mi < 4; mi++)
                ldsm_x4(af[mi], aBase + (uint32_t)((m0 + mi * 16 + (lane & 15)) * 144
                                                   + (k0h + ((lane >> 4) << 3)) * 2));
#pragma unroll
            for (int p = 0; p < 2; p++) {
                const int row = n0 + p * 16 + (lane & 7) + ((lane >> 4) << 3);
                const int kadd = ((lane >> 3) & 1) << 3;
                ldsm_x4(bf[p], bBase + (uint32_t)(row * 144 + (k0h + kadd) * 2));
            }
#pragma unroll
            for (int mi = 0; mi < 4; mi++)
#pragma unroll
                for (int ni = 0; ni < 4; ni++)
                    mma_f16(acc[mi][ni], af[mi], &bf[ni >> 1][(ni & 1) * 2]);
        }
        __syncthreads();
    }

    if (bn < 512) {
        // U columns -> fp32 g_u (direct stores: 32B segments = full sectors)
#pragma unroll
        for (int mi = 0; mi < 4; mi++)
#pragma unroll
            for (int ni = 0; ni < 4; ni++) {
                const int r = bm + m0 + mi * 16 + gid;
                const int c = n0 + ni * 8 + 2 * tig;
                *(float2*)&g_u[(size_t)r * LH + bn + c]       = make_float2(acc[mi][ni][0], acc[mi][ni][1]);
                *(float2*)&g_u[(size_t)(r + 8) * LH + bn + c] = make_float2(acc[mi][ni][2], acc[mi][ni][3]);
            }
    } else {
        // V/Q/K -> fp16 staged through smem for coalesced 16B stores
        __half (*sout)[136] = reinterpret_cast<__half(*)[136]>(sh);
        // mainloop smem reads are fenced by the trailing __syncthreads() of it=7
#pragma unroll
        for (int mi = 0; mi < 4; mi++)
#pragma unroll
            for (int ni = 0; ni < 4; ni++) {
                const int r = m0 + mi * 16 + gid;
                const int c = n0 + ni * 8 + 2 * tig;
                *(__half2*)&sout[r][c]     = __floats2half2_rn(acc[mi][ni][0], acc[mi][ni][1]);
                *(__half2*)&sout[r + 8][c] = __floats2half2_rn(acc[mi][ni][2], acc[mi][ni][3]);
            }
        __syncthreads();
        const int qc0 = bn - 512;
#pragma unroll
        for (int i = 0; i < 8; i++) {
            const int idx = t + i * 256;          // 0..2047
            const int row = idx >> 4, ch = idx & 15;
            *(float4*)&g_qkv[(size_t)(bm + row) * QKV_W + qc0 + ch * 8] =
                *(float4*)&sout[row][ch * 8];
        }
    }
}

// ---------------- 3) causal silu-attention: f16-accum S GEMM, register P ----------------
// grid (32 bh, 16 q-tiles), 128 threads = 4 warps; warp owns 32 q-rows x 64-key tiles (32-key subtiles).
// smem (halves): 4-stage KV ring, stage s @ s*9216: K [64][72] @0, V @4608.
// Q staged in stage 3 (dead after fragment extraction at pair 0, then reused by the ring).
#define ATTN_SMEM (4 * 9216 * 2)   // 73728 B
__global__ __launch_bounds__(128, 3) void attn_kernel() {
    extern __shared__ __half sh[];

    const int t = threadIdx.x;
    const int wid = t >> 5, lane = t & 31;
    const int gid = lane >> 2, tig = lane & 3;

    const int nt = 15 - blockIdx.y;     // largest workloads in wave 1
    const int bh = blockIdx.x;
    const int b = bh >> 3, h = bh & 7;
    const int nbase = nt << 7;
    const size_t base = (size_t)b * SS;
    const int hd = h << 6;

    const int qrow = wid * 32;                  // warp's local Q-row base (32 rows)
    const int rowmin = nbase + qrow;            // warp's min global q-row

    const int lrow = t >> 3, lq = t & 7;        // loaders (128 threads)

#define LOAD_KV_ST(st, m0b) do {                                                        \
        __half* sk = sh + (st) * 9216;                                                  \
        __half* sv = sk + 4608;                                                         \
        _Pragma("unroll")                                                               \
        for (int i = 0; i < 4; i++) {                                                   \
            const int row = lrow + i * 16;                                              \
            const __half* rowp = &g_qkv[(base + (m0b) + row) * QKV_W + hd + lq * 8];    \
            cpa16(sk + row * 72 + lq * 8, rowp + QO_K);                                 \
            cpa16(sv + row * 72 + lq * 8, rowp + QO_V);                                 \
        }                                                                               \
    } while (0)

    const int nkt = 2 * nt + 2;                 // always even, >= 2

    // Preload: Q -> stage 3 region, then KV tiles 0,1,2 (clamped)
    {
        __half* qd = sh + 3 * 9216;
#pragma unroll
        for (int i = 0; i < 8; i++) {
            const int row = lrow + i * 16;
            cpa16(qd + row * 72 + lq * 8,
                  &g_qkv[(base + nbase + row) * QKV_W + QO_Q + hd + lq * 8]);
        }
    }
    LOAD_KV_ST(0, 0); cp_commit();
    LOAD_KV_ST(1, 64); cp_commit();
    { const int t2i = (2 < nkt) ? 2 : nkt - 1; LOAD_KV_ST(2, t2i << 6); cp_commit(); }

    uint32_t aq[2][4][4];       // Q fragments, loop-resident
    float o[2][8][4] = {};

    const int npair = nkt >> 1;
    for (int p = 0; p < npair; ++p) {
        cp_wait0();
        __syncthreads();
        if (p == 0) {
            const uint32_t qBase = smem_u32(sh + 3 * 9216);
#pragma unroll
            for (int g = 0; g < 2; g++)
#pragma unroll
                for (int ks = 0; ks < 4; ks++)
                    ldsm_x4(aq[g][ks], qBase +
                            (uint32_t)((qrow + g * 16 + (lane & 15)) * 144
                                       + (ks * 16 + ((lane >> 4) << 3)) * 2));
            __syncthreads();    // fence Q reads before stage-3 prefetch below
        }
        // prefetch tiles 2p+2, 2p+3 into stages consumed last pair (safe post-sync)
        if (2 * p + 2 < nkt) { LOAD_KV_ST((2 * p + 2) & 3, (2 * p + 2) << 6); cp_commit(); }
        if (2 * p + 3 < nkt) { LOAD_KV_ST((2 * p + 3) & 3, (2 * p + 3) << 6); cp_commit(); }

        // process kt = 2p, 2p+1 back-to-back, no intervening sync
#pragma unroll
        for (int hf = 0; hf < 2; hf++) {
            const int kt = 2 * p + hf;
            const uint32_t kBase = smem_u32(sh + (kt & 3) * 9216);
            const uint32_t vBase = kBase + 9216;    // +4608 halves
            const int m0b = kt << 6;

#pragma unroll
            for (int sub = 0; sub < 2; sub++) {
                const int s32 = m0b + sub * 32;
                if (s32 > rowmin + 31) continue;        // subtile fully masked (warp-uniform)

                // ---- S = Q(32x64) @ K^T(64x32), f16 accumulation ----
                uint32_t s2[2][4][2] = {};              // packed half2 accumulators
#pragma unroll
                for (int ks = 0; ks < 4; ks++) {
                    const int d0h = ks * 16;
                    uint32_t bk[2][4];
#pragma unroll
                    for (int pp = 0; pp < 2; pp++) {
                        const int row = sub * 32 + pp * 16 + (lane & 7) + ((lane >> 4) << 3);
                        const int kadd = ((lane >> 3) & 1) << 3;
                        ldsm_x4(bk[pp], kBase + (uint32_t)(row * 144 + (d0h + kadd) * 2));
                    }
#pragma unroll
                    for (int g = 0; g < 2; g++)
#pragma unroll
                        for (int nb = 0; nb < 4; nb++)
                            mma_f16acc(s2[g][nb], aq[g][ks], &bk[nb >> 1][(nb & 1) * 2]);
                }

                // ---- causal mask (partial subtiles only; exact-int fp16 compare) ----
                if (s32 + 31 > rowmin) {
#pragma unroll
                    for (int g = 0; g < 2; g++) {
                        const float rbase = (float)(rowmin + g * 16 + gid);
#pragma unroll
                        for (int nb = 0; nb < 4; nb++) {
                            const int mm = s32 + nb * 8 + 2 * tig;
                            const __half2 cols = __floats2half2_rn((float)mm, (float)(mm + 1));
#pragma unroll
                            for (int rg = 0; rg < 2; rg++) {
                                const __half2 rows = __half2half2(__float2half(rbase + rg * 8));
                                const __half2 keep = __hle2(cols, rows);   // col<=row -> 1.0
                                s2[g][nb][rg] = h2u(__hmul2(u2h(s2[g][nb][rg]), keep));
                            }
                        }
                    }
                }

                // ---- silu (f16x2) directly on accumulator regs = A-fragments ----
                uint32_t pf[2][2][4];
#pragma unroll
                for (int g = 0; g < 2; g++)
#pragma unroll
                    for (int kb = 0; kb < 2; kb++) {
                        pf[g][kb][0] = silu2(s2[g][2 * kb][0]);
                        pf[g][kb][1] = silu2(s2[g][2 * kb][1]);
                        pf[g][kb][2] = silu2(s2[g][2 * kb + 1][0]);
                        pf[g][kb][3] = silu2(s2[g][2 * kb + 1][1]);
                    }

                // ---- O += P(32x32) @ V(32x64), fp32 accumulation ----
#pragma unroll
                for (int kb = 0; kb < 2; kb++) {
                    const int mk = sub * 32 + kb * 16;
                    uint32_t bv[4][4];
#pragma unroll
                    for (int db = 0; db < 4; db++) {
                        const int row = mk + (lane & 7) + (((lane >> 3) & 1) << 3);
                        const int col = db * 16 + ((lane >> 4) << 3);
                        ldsm_x4_t(bv[db], vBase + (uint32_t)(row * 144 + col * 2));
                    }
#pragma unroll
                    for (int g = 0; g < 2; g++)
#pragma unroll
                        for (int dnb = 0; dnb < 8; dnb++)
                            mma_f16(o[g][dnb], pf[g][kb], &bv[dnb >> 1][(dnb & 1) * 2]);
                }
            }
        }
    }

    // ---- write O ----
#pragma unroll
    for (int g = 0; g < 2; g++)
#pragma unroll
        for (int dnb = 0; dnb < 8; dnb++) {
            const size_t r = base + rowmin + g * 16 + gid;
            const int c = hd + dnb * 8 + 2 * tig;
            *(float2*)&g_attn[r * LH + c]       = make_float2(o[g][dnb][0], o[g][dnb][1]);
            *(float2*)&g_attn[(r + 8) * LH + c] = make_float2(o[g][dnb][2], o[g][dnb][3]);
        }
}

// ---------------- 4) output LN * u + residual (float4) ----------------
__global__ __launch_bounds__(128) void out_kernel(const float* __restrict__ ue,
                                                  const float* __restrict__ g,
                                                  const float* __restrict__ be,
                                                  float* __restrict__ out) {
    const int row = blockIdx.x, t = threadIdx.x;
    const float4 a = *(const float4*)&g_attn[(size_t)row * LH + 4 * t];
    float2 r = block_reduce_sum2_128(a.x + a.y + a.z + a.w,
                                     a.x * a.x + a.y * a.y + a.z * a.z + a.w * a.w);
    float mu = r.x * (1.f / 512.f);
    float var = r.y * (1.f / 512.f) - mu * mu;
    float rs = rsqrtf(var + 1e-6f);
    const float4 gg = *(const float4*)&g[4 * t];
    const float4 bb = *(const float4*)&be[4 * t];
    const float4 uu = *(const float4*)&g_u[(size_t)row * LH + 4 * t];
    const float4 ee = *(const float4*)&ue[(size_t)row * EE + 4 * t];
    float4 yy;
    yy.x = ee.x + ((a.x - mu) * rs * gg.x + bb.x) * uu.x;
    yy.y = ee.y + ((a.y - mu) * rs * gg.y + bb.y) * uu.y;
    yy.z = ee.z + ((a.z - mu) * rs * gg.z + bb.z) * uu.z;
    yy.w = ee.w + ((a.w - mu) * rs * gg.w + bb.w) * uu.w;
    *(float4*)&out[(size_t)row * EE + 4 * t] = yy;
}

extern "C" void kernel_launch(void* const* d_in, const int* in_sizes, int n_in,
                              void* d_out, int out_size) {
    (void)in_sizes; (void)n_in; (void)out_size;
    const float* ue   = (const float*)d_in[0];
    const float* uvqk = (const float*)d_in[2];
    const float* ing  = (const float*)d_in[3];
    const float* inb  = (const float*)d_in[4];
    const float* outg = (const float*)d_in[5];
    const float* outb = (const float*)d_in[6];
    float* out = (float*)d_out;

    cudaFuncSetAttribute(gemm_proj_kernel, cudaFuncAttributeMaxDynamicSharedMemorySize, PROJ_SMEM);
    cudaFuncSetAttribute(attn_kernel, cudaFuncAttributeMaxDynamicSharedMemorySize, ATTN_SMEM);

    ln_in_kernel<<<NROW, 128>>>(ue, ing, inb);
    transpose_w_kernel<<<dim3(FF / 32, EE / 32), dim3(32, 8)>>>(uvqk);
    gemm_proj_kernel<<<dim3(FF / 128, NROW / 128), 256, PROJ_SMEM>>>();
    attn_kernel<<<dim3(BB * HH, SS / 128), 128, ATTN_SMEM>>>();
    out_kernel<<<NROW, 128>>>(ue, outg, outb, out);
}

// round 15
// speedup vs baseline: 1.0172x; 1.0172x over previous
#include <cuda_runtime.h>
#include <cuda_fp16.h>
#include <math.h>
#include <stdint.h>

#define EE 512
#define HH 8
#define BB 4
#define SS 2048
#define NROW (BB*SS)            // 8192
#define FF 2048                 // 2LH + 2AH
#define LH 512

// unified proj output, fp16, per row: U @0, V @512, Q @1024, K @1536
#define PW 2048
#define PO_V 512
#define PO_Q 1024
#define PO_K 1536

// Scratch (allocation-free rule: __device__ globals)
__device__ __half g_normed[(size_t)NROW*EE];   // 8.4 MB
__device__ __half g_Wt[(size_t)FF*EE];         // 2 MB (W transposed, fp16)
__device__ __half g_qkvu[(size_t)NROW*PW];     // 33.6 MB (U,V,Q,K fp16)
__device__ __half g_attn16[(size_t)NROW*LH];   // 8.4 MB

// ---------------- helpers ----------------
__device__ __forceinline__ uint32_t h2u(__half2 h) {
    uint32_t u;
    memcpy(&u, &h, 4);
    return u;
}
__device__ __forceinline__ __half2 u2h(uint32_t u) {
    __half2 h;
    memcpy(&h, &u, 4);
    return h;
}
// silu on packed half2: y = 0.5x + 0.5x*tanh(0.5x)  (exact tails via tanh saturation)
__device__ __forceinline__ uint32_t silu2(uint32_t x2) {
    __half2 x = u2h(x2);
    __half2 hx = __hmul2(x, __half2half2(__float2half(0.5f)));
    uint32_t hxu = h2u(hx), thu;
    asm("tanh.approx.f16x2 %0, %1;" : "=r"(thu) : "r"(hxu));
    __half2 y = __hfma2(hx, u2h(thu), hx);
    return h2u(y);
}
__device__ __forceinline__ void cpa16(void* dst, const void* src) {
    unsigned u = (unsigned)__cvta_generic_to_shared(dst);
    asm volatile("cp.async.cg.shared.global [%0], [%1], 16;\n" :: "r"(u), "l"(src));
}
__device__ __forceinline__ void cp_commit() { asm volatile("cp.async.commit_group;\n"); }
__device__ __forceinline__ void cp_wait0() { asm volatile("cp.async.wait_group 0;\n"); }
__device__ __forceinline__ void cp_wait1() { asm volatile("cp.async.wait_group 1;\n"); }

__device__ __forceinline__ uint32_t smem_u32(const void* p) {
    return (uint32_t)__cvta_generic_to_shared(p);
}
__device__ __forceinline__ void ldsm_x4(uint32_t* r, uint32_t addr) {
    asm volatile("ldmatrix.sync.aligned.m8n8.x4.shared.b16 {%0,%1,%2,%3}, [%4];"
                 : "=r"(r[0]), "=r"(r[1]), "=r"(r[2]), "=r"(r[3]) : "r"(addr));
}
__device__ __forceinline__ void ldsm_x4_t(uint32_t* r, uint32_t addr) {
    asm volatile("ldmatrix.sync.aligned.m8n8.x4.trans.shared.b16 {%0,%1,%2,%3}, [%4];"
                 : "=r"(r[0]), "=r"(r[1]), "=r"(r[2]), "=r"(r[3]) : "r"(addr));
}
__device__ __forceinline__ void mma_f16(float* d, const uint32_t* a, const uint32_t* b) {
    asm volatile(
        "mma.sync.aligned.m16n8k16.row.col.f32.f16.f16.f32 "
        "{%0,%1,%2,%3}, {%4,%5,%6,%7}, {%8,%9}, {%0,%1,%2,%3};\n"
        : "+f"(d[0]), "+f"(d[1]), "+f"(d[2]), "+f"(d[3])
        : "r"(a[0]), "r"(a[1]), "r"(a[2]), "r"(a[3]), "r"(b[0]), "r"(b[1]));
}
// f16 accumulation; D-fragment layout == A-fragment layout of next mma
__device__ __forceinline__ void mma_f16acc(uint32_t* d, const uint32_t* a, const uint32_t* b) {
    asm volatile(
        "mma.sync.aligned.m16n8k16.row.col.f16.f16.f16.f16 "
        "{%0,%1}, {%2,%3,%4,%5}, {%6,%7}, {%0,%1};\n"
        : "+r"(d[0]), "+r"(d[1])
        : "r"(a[0]), "r"(a[1]), "r"(a[2]), "r"(a[3]), "r"(b[0]), "r"(b[1]));
}

__device__ __forceinline__ float2 block_reduce_sum2_128(float sum, float sq) {
    __shared__ float sh[8];
    int lane = threadIdx.x & 31, w = threadIdx.x >> 5;
#pragma unroll
    for (int o = 16; o > 0; o >>= 1) {
        sum += __shfl_xor_sync(0xffffffffu, sum, o);
        sq  += __shfl_xor_sync(0xffffffffu, sq, o);
    }
    if (lane == 0) { sh[w] = sum; sh[4 + w] = sq; }
    __syncthreads();
    float s = 0.f, q = 0.f;
#pragma unroll
    for (int i = 0; i < 4; i++) { s += sh[i]; q += sh[4 + i]; }
    return make_float2(s, q);
}

// ---------------- 1) fused: input LayerNorm (blocks 0..8191) + W transpose (blocks 8192..9215) ----------------
__global__ __launch_bounds__(256) void ln_tr_kernel(const float* __restrict__ x,
                                                    const float* __restrict__ g,
                                                    const float* __restrict__ be,
                                                    const float* __restrict__ W) {
    __shared__ float smbuf[32 * 33];    // transpose tile; ln uses first 16 floats
    const int t = threadIdx.x;
    if (blockIdx.x < NROW) {
        // ---- LayerNorm row ----
        const int row = blockIdx.x;
        const float2 v = *(const float2*)&x[(size_t)row * EE + 2 * t];
        // 256-thread reduce
        float sum = v.x + v.y, sq = v.x * v.x + v.y * v.y;
        int lane = t & 31, w = t >> 5;
#pragma unroll
        for (int o = 16; o > 0; o >>= 1) {
            sum += __shfl_xor_sync(0xffffffffu, sum, o);
            sq  += __shfl_xor_sync(0xffffffffu, sq, o);
        }
        if (lane == 0) { smbuf[w] = sum; smbuf[8 + w] = sq; }
        __syncthreads();
        float s = 0.f, q = 0.f;
#pragma unroll
        for (int i = 0; i < 8; i++) { s += smbuf[i]; q += smbuf[8 + i]; }
        float mu = s * (1.f / 512.f);
        float var = q * (1.f / 512.f) - mu * mu;
        float rs = rsqrtf(var + 1e-6f);
        const float2 gg = *(const float2*)&g[2 * t];
        const float2 bb = *(const float2*)&be[2 * t];
        float y0 = (v.x - mu) * rs * gg.x + bb.x;
        float y1 = (v.y - mu) * rs * gg.y + bb.y;
        ((__half2*)(g_normed + (size_t)row * EE))[t] = __floats2half2_rn(y0, y1);
    } else {
        // ---- W transpose tile ----
        float (*tile)[33] = reinterpret_cast<float(*)[33]>(smbuf);
        const int tb = blockIdx.x - NROW;
        const int n0 = (tb & 63) * 32, k0 = (tb >> 6) * 32;
        const int tx = t & 31, ty = t >> 5;   // 32 x 8
#pragma unroll
        for (int j = 0; j < 4; j++)
            tile[ty + j * 8][tx] = W[(size_t)(k0 + ty + j * 8) * FF + n0 + tx];
        __syncthreads();
#pragma unroll
        for (int j = 0; j < 4; j++)
            g_Wt[(size_t)(n0 + ty + j * 8) * EE + k0 + tx] = __float2half(tile[tx][ty + j * 8]);
    }
}

// ---------------- 2) projection GEMM (fp16 mma m16n8k16 + ldmatrix) ----------------
// 128x128 tile, BK=64, 256 threads = 8 warps (2m x 4n), warp tile 64x32.
// Epilogue: all outputs fp16 -> g_qkvu, staged via smem for 16B-coalesced stores.
#define PROJ_SMEM (4 * 128 * 72 * 2)   // 73728 B
__global__ __launch_bounds__(256, 2) void gemm_proj_kernel() {
    extern __shared__ __half sh[];
    const int t = threadIdx.x;
    const int wid = t >> 5, lane = t & 31;
    const int gid = lane >> 2, tig = lane & 3;
    const int warp_m = wid & 1, warp_n = wid >> 1;
    const int m0 = warp_m * 64, n0 = warp_n * 32;
    const int bm = blockIdx.y * 128, bn = blockIdx.x * 128;

    float acc[4][4][4] = {};

#define PJ_LOAD(st, k0) do {                                                           \
        __half* sA = sh + (st) * 9216;                                                 \
        __half* sB = sh + 18432 + (st) * 9216;                                         \
        _Pragma("unroll")                                                              \
        for (int i = 0; i < 4; i++) {                                                  \
            const int gidx = t + i * 256;                                              \
            const int row = gidx >> 3, q = gidx & 7;                                   \
            cpa16(sA + row * 72 + q * 8, &g_normed[(size_t)(bm + row) * EE + (k0) + q * 8]); \
            cpa16(sB + row * 72 + q * 8, &g_Wt[(size_t)(bn + row) * EE + (k0) + q * 8]);    \
        }                                                                              \
    } while (0)

    PJ_LOAD(0, 0); cp_commit();

    for (int it = 0; it < 8; ++it) {
        if (it < 7) { PJ_LOAD((it + 1) & 1, (it + 1) * 64); cp_commit(); cp_wait1(); }
        else cp_wait0();
        __syncthreads();
        const int st = it & 1;
        const uint32_t aBase = smem_u32(sh + st * 9216);
        const uint32_t bBase = smem_u32(sh + 18432 + st * 9216);
#pragma unroll
        for (int ks = 0; ks < 4; ks++) {
            const int k0h = ks * 16;
            uint32_t af[4][4], bf[2][4];
#pragma unroll
            for (int mi = 0; mi < 4; mi++)
                ldsm_x4(af[mi], aBase + (uint32_t)((m0 + mi * 16 + (lane & 15)) * 144
                                                   + (k0h + ((lane >> 4) << 3)) * 2));
#pragma unroll
            for (int p = 0; p < 2; p++) {
                const int row = n0 + p * 16 + (lane & 7) + ((lane >> 4) << 3);
                const int kadd = ((lane >> 3) & 1) << 3;
                ldsm_x4(bf[p], bBase + (uint32_t)(row * 144 + (k0h + kadd) * 2));
            }
#pragma unroll
            for (int mi = 0; mi < 4; mi++)
#pragma unroll
                for (int ni = 0; ni < 4; ni++)
                    mma_f16(acc[mi][ni], af[mi], &bf[ni >> 1][(ni & 1) * 2]);
        }
        __syncthreads();
    }

    // epilogue: all outputs -> fp16 via smem stage, 16B-coalesced stores
    {
        __half (*sout)[136] = reinterpret_cast<__half(*)[136]>(sh);
        // mainloop smem reads fenced by the trailing __syncthreads() of it=7
#pragma unroll
        for (int mi = 0; mi < 4; mi++)
#pragma unroll
            for (int ni = 0; ni < 4; ni++) {
                const int r = m0 + mi * 16 + gid;
                const int c = n0 + ni * 8 + 2 * tig;
                *(__half2*)&sout[r][c]     = __floats2half2_rn(acc[mi][ni][0], acc[mi][ni][1]);
                *(__half2*)&sout[r + 8][c] = __floats2half2_rn(acc[mi][ni][2], acc[mi][ni][3]);
            }
        __syncthreads();
#pragma unroll
        for (int i = 0; i < 8; i++) {
            const int idx = t + i * 256;          // 0..2047
            const int row = idx >> 4, ch = idx & 15;
            *(float4*)&g_qkvu[(size_t)(bm + row) * PW + bn + ch * 8] =
                *(float4*)&sout[row][ch * 8];
        }
    }
}

// ---------------- 3) causal silu-attention: f16-accum S GEMM, register P ----------------
// grid (32 bh, 16 q-tiles), 128 threads = 4 warps; warp owns 32 q-rows x 64-key tiles (32-key subtiles).
// smem (halves): 4-stage KV ring, stage s @ s*9216: K [64][72] @0, V @4608.
// Q staged in stage 3 (dead after fragment extraction at pair 0, then reused by the ring).
#define ATTN_SMEM (4 * 9216 * 2)   // 73728 B
__global__ __launch_bounds__(128, 3) void attn_kernel() {
    extern __shared__ __half sh[];

    const int t = threadIdx.x;
    const int wid = t >> 5, lane = t & 31;
    const int gid = lane >> 2, tig = lane & 3;

    const int nt = 15 - blockIdx.y;     // largest workloads in wave 1
    const int bh = blockIdx.x;
    const int b = bh >> 3, h = bh & 7;
    const int nbase = nt << 7;
    const size_t base = (size_t)b * SS;
    const int hd = h << 6;

    const int qrow = wid * 32;                  // warp's local Q-row base (32 rows)
    const int rowmin = nbase + qrow;            // warp's min global q-row

    const int lrow = t >> 3, lq = t & 7;        // loaders (128 threads)

#define LOAD_KV_ST(st, m0b) do {                                                        \
        __half* sk = sh + (st) * 9216;                                                  \
        __half* sv = sk + 4608;                                                         \
        _Pragma("unroll")                                                               \
        for (int i = 0; i < 4; i++) {                                                   \
            const int row = lrow + i * 16;                                              \
            const __half* rowp = &g_qkvu[(base + (m0b) + row) * PW + hd + lq * 8];      \
            cpa16(sk + row * 72 + lq * 8, rowp + PO_K);                                 \
            cpa16(sv + row * 72 + lq * 8, rowp + PO_V);                                 \
        }                                                                               \
    } while (0)

    const int nkt = 2 * nt + 2;                 // always even, >= 2

    // Preload: Q -> stage 3 region, then KV tiles 0,1,2 (clamped)
    {
        __half* qd = sh + 3 * 9216;
#pragma unroll
        for (int i = 0; i < 8; i++) {
            const int row = lrow + i * 16;
            cpa16(qd + row * 72 + lq * 8,
                  &g_qkvu[(base + nbase + row) * PW + PO_Q + hd + lq * 8]);
        }
    }
    LOAD_KV_ST(0, 0); cp_commit();
    LOAD_KV_ST(1, 64); cp_commit();
    { const int t2i = (2 < nkt) ? 2 : nkt - 1; LOAD_KV_ST(2, t2i << 6); cp_commit(); }

    uint32_t aq[2][4][4];       // Q fragments, loop-resident
    float o[2][8][4] = {};

    const int npair = nkt >> 1;
    for (int p = 0; p < npair; ++p) {
        cp_wait0();
        __syncthreads();
        if (p == 0) {
            const uint32_t qBase = smem_u32(sh + 3 * 9216);
#pragma unroll
            for (int g = 0; g < 2; g++)
#pragma unroll
                for (int ks = 0; ks < 4; ks++)
                    ldsm_x4(aq[g][ks], qBase +
                            (uint32_t)((qrow + g * 16 + (lane & 15)) * 144
                                       + (ks * 16 + ((lane >> 4) << 3)) * 2));
            __syncthreads();    // fence Q reads before stage-3 prefetch below
        }
        // prefetch tiles 2p+2, 2p+3 into stages consumed last pair (safe post-sync)
        if (2 * p + 2 < nkt) { LOAD_KV_ST((2 * p + 2) & 3, (2 * p + 2) << 6); cp_commit(); }
        if (2 * p + 3 < nkt) { LOAD_KV_ST((2 * p + 3) & 3, (2 * p + 3) << 6); cp_commit(); }

        // process kt = 2p, 2p+1 back-to-back, no intervening sync
#pragma unroll
        for (int hf = 0; hf < 2; hf++) {
            const int kt = 2 * p + hf;
            const uint32_t kBase = smem_u32(sh + (kt & 3) * 9216);
            const uint32_t vBase = kBase + 9216;    // +4608 halves
            const int m0b = kt << 6;

#pragma unroll
            for (int sub = 0; sub < 2; sub++) {
                const int s32 = m0b + sub * 32;
                if (s32 > rowmin + 31) continue;        // subtile fully masked (warp-uniform)

                // ---- S = Q(32x64) @ K^T(64x32), f16 accumulation ----
                uint32_t s2[2][4][2] = {};              // packed half2 accumulators
#pragma unroll
                for (int ks = 0; ks < 4; ks++) {
                    const int d0h = ks * 16;
                    uint32_t bk[2][4];
#pragma unroll
                    for (int pp = 0; pp < 2; pp++) {
                        const int row = sub * 32 + pp * 16 + (lane & 7) + ((lane >> 4) << 3);
                        const int kadd = ((lane >> 3) & 1) << 3;
                        ldsm_x4(bk[pp], kBase + (uint32_t)(row * 144 + (d0h + kadd) * 2));
                    }
#pragma unroll
                    for (int g = 0; g < 2; g++)
#pragma unroll
                        for (int nb = 0; nb < 4; nb++)
                            mma_f16acc(s2[g][nb], aq[g][ks], &bk[nb >> 1][(nb & 1) * 2]);
                }

                // ---- causal mask (partial subtiles only; exact-int fp16 compare) ----
                if (s32 + 31 > rowmin) {
#pragma unroll
                    for (int g = 0; g < 2; g++) {
                        const float rbase = (float)(rowmin + g * 16 + gid);
#pragma unroll
                        for (int nb = 0; nb < 4; nb++) {
                            const int mm = s32 + nb * 8 + 2 * tig;
                            const __half2 cols = __floats2half2_rn((float)mm, (float)(mm + 1));
#pragma unroll
                            for (int rg = 0; rg < 2; rg++) {
                                const __half2 rows = __half2half2(__float2half(rbase + rg * 8));
                                const __half2 keep = __hle2(cols, rows);   // col<=row -> 1.0
                                s2[g][nb][rg] = h2u(__hmul2(u2h(s2[g][nb][rg]), keep));
                            }
                        }
                    }
                }

                // ---- silu (f16x2) directly on accumulator regs = A-fragments ----
                uint32_t pf[2][2][4];
#pragma unroll
                for (int g = 0; g < 2; g++)
#pragma unroll
                    for (int kb = 0; kb < 2; kb++) {
                        pf[g][kb][0] = silu2(s2[g][2 * kb][0]);
                        pf[g][kb][1] = silu2(s2[g][2 * kb][1]);
                        pf[g][kb][2] = silu2(s2[g][2 * kb + 1][0]);
                        pf[g][kb][3] = silu2(s2[g][2 * kb + 1][1]);
                    }

                // ---- O += P(32x32) @ V(32x64), fp32 accumulation ----
#pragma unroll
                for (int kb = 0; kb < 2; kb++) {
                    const int mk = sub * 32 + kb * 16;
                    uint32_t bv[4][4];
#pragma unroll
                    for (int db = 0; db < 4; db++) {
                        const int row = mk + (lane & 7) + (((lane >> 3) & 1) << 3);
                        const int col = db * 16 + ((lane >> 4) << 3);
                        ldsm_x4_t(bv[db], vBase + (uint32_t)(row * 144 + col * 2));
                    }
#pragma unroll
                    for (int g = 0; g < 2; g++)
#pragma unroll
                        for (int dnb = 0; dnb < 8; dnb++)
                            mma_f16(o[g][dnb], pf[g][kb], &bv[dnb >> 1][(dnb & 1) * 2]);
                }
            }
        }
    }

    // ---- write O (fp16) ----
#pragma unroll
    for (int g = 0; g < 2; g++)
#pragma unroll
        for (int dnb = 0; dnb < 8; dnb++) {
            const size_t r = base + rowmin + g * 16 + gid;
            const int c = hd + dnb * 8 + 2 * tig;
            *(__half2*)&g_attn16[r * LH + c]       = __floats2half2_rn(o[g][dnb][0], o[g][dnb][1]);
            *(__half2*)&g_attn16[(r + 8) * LH + c] = __floats2half2_rn(o[g][dnb][2], o[g][dnb][3]);
        }
}

// ---------------- 4) output LN * u + residual ----------------
__global__ __launch_bounds__(128) void out_kernel(const float* __restrict__ ue,
                                                  const float* __restrict__ g,
                                                  const float* __restrict__ be,
                                                  float* __restrict__ out) {
    const int row = blockIdx.x, t = threadIdx.x;
    const __half2* ar = (const __half2*)(g_attn16 + (size_t)row * LH);
    const float2 a01 = __half22float2(ar[2 * t]);
    const float2 a23 = __half22float2(ar[2 * t + 1]);
    float2 r = block_reduce_sum2_128(a01.x + a01.y + a23.x + a23.y,
                                     a01.x * a01.x + a01.y * a01.y + a23.x * a23.x + a23.y * a23.y);
    float mu = r.x * (1.f / 512.f);
    float var = r.y * (1.f / 512.f) - mu * mu;
    float rs = rsqrtf(var + 1e-6f);
    const float4 gg = *(const float4*)&g[4 * t];
    const float4 bb = *(const float4*)&be[4 * t];
    const __half2* ur = (const __half2*)(g_qkvu + (size_t)row * PW);
    const float2 u01 = __half22float2(ur[2 * t]);
    const float2 u23 = __half22float2(ur[2 * t + 1]);
    const float4 ee = *(const float4*)&ue[(size_t)row * EE + 4 * t];
    float4 yy;
    yy.x = ee.x + ((a01.x - mu) * rs * gg.x + bb.x) * u01.x;
    yy.y = ee.y + ((a01.y - mu) * rs * gg.y + bb.y) * u01.y;
    yy.z = ee.z + ((a23.x - mu) * rs * gg.z + bb.z) * u23.x;
    yy.w = ee.w + ((a23.y - mu) * rs * gg.w + bb.w) * u23.y;
    *(float4*)&out[(size_t)row * EE + 4 * t] = yy;
}

extern "C" void kernel_launch(void* const* d_in, const int* in_sizes, int n_in,
                              void* d_out, int out_size) {
    (void)in_sizes; (void)n_in; (void)out_size;
    const float* ue   = (const float*)d_in[0];
    const float* uvqk = (const float*)d_in[2];
    const float* ing  = (const float*)d_in[3];
    const float* inb  = (const float*)d_in[4];
    const float* outg = (const float*)d_in[5];
    const float* outb = (const float*)d_in[6];
    float* out = (float*)d_out;

    cudaFuncSetAttribute(gemm_proj_kernel, cudaFuncAttributeMaxDynamicSharedMemorySize, PROJ_SMEM);
    cudaFuncSetAttribute(attn_kernel, cudaFuncAttributeMaxDynamicSharedMemorySize, ATTN_SMEM);

    ln_tr_kernel<<<NROW + (FF / 32) * (EE / 32), 256>>>(ue, ing, inb, uvqk);
    gemm_proj_kernel<<<dim3(FF / 128, NROW / 128), 256, PROJ_SMEM>>>();
    attn_kernel<<<dim3(BB * HH, SS / 128), 128, ATTN_SMEM>>>();
    out_kernel<<<NROW, 128>>>(ue, outg, outb, out);
}